// round 1
// baseline (speedup 1.0000x reference)
#include <cuda_runtime.h>
#include <math.h>

#define TSTEPS 20
#define BATCH  128
#define EDIM   512
#define HDIM   512
#define GDIM   2048   // 4*HDIM
#define VOCAB  32000
#define CAPLEN 20

// ---------------- device scratch (no allocation allowed) ----------------
__device__ float d_xseq [TSTEPS * BATCH * EDIM];   // 5.2 MB
__device__ float d_xw   [TSTEPS * BATCH * GDIM];   // 21 MB
__device__ float d_gates[BATCH * GDIM];            // 1 MB
__device__ float d_hstate[BATCH * HDIM];
__device__ float d_cstate[BATCH * HDIM];
__device__ float d_hall [TSTEPS * BATCH * HDIM];   // 5.2 MB
__device__ float d_hc   [TSTEPS * BATCH * HDIM];   // 5.2 MB (compact rows)
__device__ int   d_off  [TSTEPS + 1];

// ---------------- pack offsets: off[t] = sum_{t'<t} #{lengths > t'} ------
__global__ void compute_off_kernel(const int* __restrict__ lengths,
                                   int* __restrict__ off) {
    __shared__ int sl[BATCH];
    __shared__ int cnt[TSTEPS];
    int tid = threadIdx.x;
    if (tid < BATCH) sl[tid] = lengths[tid];
    __syncthreads();
    if (tid < TSTEPS) {
        int c = 0;
        #pragma unroll 8
        for (int b = 0; b < BATCH; b++) c += (sl[b] > tid);
        cnt[tid] = c;
    }
    __syncthreads();
    if (tid == 0) {
        int acc = 0;
        for (int t = 0; t < TSTEPS; t++) { off[t] = acc; acc += cnt[t]; }
        off[TSTEPS] = acc;
    }
}

// ---------------- build teacher-forced input sequence -------------------
// xseq[t][b][:] = (t==0) ? features[b] : embed_w[captions[b][t-1]]
__global__ void build_xseq_kernel(const float* __restrict__ features,
                                  const int*   __restrict__ captions,
                                  const float* __restrict__ embed_w,
                                  float* __restrict__ xseq) {
    int gid = blockIdx.x * blockDim.x + threadIdx.x;   // over T*B*E/4
    int e4  = gid % (EDIM / 4);
    int row = gid / (EDIM / 4);
    int t = row / BATCH, b = row % BATCH;
    const float4* src;
    if (t == 0) {
        src = reinterpret_cast<const float4*>(features + (size_t)b * EDIM);
    } else {
        int tok = captions[b * CAPLEN + (t - 1)];
        src = reinterpret_cast<const float4*>(embed_w + (size_t)tok * EDIM);
    }
    reinterpret_cast<float4*>(xseq)[gid] = src[e4];
}

// ---------------- LSTM pointwise cell ------------------------------------
__global__ void lstm_cell_kernel(const float* __restrict__ gates,
                                 float* __restrict__ h,
                                 float* __restrict__ c,
                                 float* __restrict__ hout) {
    int idx = blockIdx.x * blockDim.x + threadIdx.x;   // over B*H
    int b = idx / HDIM, j = idx % HDIM;
    const float* g = gates + (size_t)b * GDIM + j;
    float ig = 1.0f / (1.0f + expf(-g[0]));
    float fg = 1.0f / (1.0f + expf(-g[HDIM]));
    float gg = tanhf(g[2 * HDIM]);
    float og = 1.0f / (1.0f + expf(-g[3 * HDIM]));
    float cc = fg * c[idx] + ig * gg;
    c[idx] = cc;
    float hh = og * tanhf(cc);
    h[idx] = hh;
    hout[idx] = hh;
}

// ---------------- gather packed h rows into compact buffer ---------------
__global__ void gather_h_kernel(const float* __restrict__ hall,
                                const int* __restrict__ off,
                                float* __restrict__ hc) {
    int row = blockIdx.x;                 // t*BATCH + b
    int t = row / BATCH, b = row % BATCH;
    int cnt = off[t + 1] - off[t];
    if (b >= cnt) return;
    const float4* src = reinterpret_cast<const float4*>(hall + (size_t)row * HDIM);
    float4*       dst = reinterpret_cast<float4*>(hc + (size_t)(off[t] + b) * HDIM);
    dst[threadIdx.x] = src[threadIdx.x];  // 128 threads * float4 = 512 floats
}

// ---------------- generic NT GEMM: C = A[M,K] * B[N,K]^T (+init,+bias) ---
template<int BM, int BN, int BK, int TM, int TN>
__global__ void __launch_bounds__((BM / TM) * (BN / TN))
gemm_nt_kernel(const float* __restrict__ A, const float* __restrict__ B,
               const float* __restrict__ Cinit,
               const float* __restrict__ bias0, const float* __restrict__ bias1,
               float* __restrict__ C, int M, int N, int K) {
    constexpr int NT = (BM / TM) * (BN / TN);
    static_assert((BM * BK / 4) % NT == 0 && (BN * BK / 4) % NT == 0, "tiling");
    __shared__ float As[BK][BM];
    __shared__ float Bs[BK][BN];

    const int tid = threadIdx.x;
    const int m0 = blockIdx.y * BM;
    const int n0 = blockIdx.x * BN;
    const int tx = tid % (BN / TN);
    const int ty = tid / (BN / TN);

    float acc[TM][TN];
    #pragma unroll
    for (int i = 0; i < TM; i++)
        #pragma unroll
        for (int j = 0; j < TN; j++) acc[i][j] = 0.0f;

    for (int kt = 0; kt < K; kt += BK) {
        // A tile (guarded on M), stored transposed As[k][m]
        #pragma unroll
        for (int it = 0; it < (BM * BK / 4) / NT; it++) {
            int i = tid + it * NT;
            int m  = i / (BK / 4);
            int k4 = (i % (BK / 4)) * 4;
            float4 v = make_float4(0.f, 0.f, 0.f, 0.f);
            if (m0 + m < M)
                v = *reinterpret_cast<const float4*>(A + (size_t)(m0 + m) * K + kt + k4);
            As[k4 + 0][m] = v.x; As[k4 + 1][m] = v.y;
            As[k4 + 2][m] = v.z; As[k4 + 3][m] = v.w;
        }
        // B tile (N always divisible by BN here)
        #pragma unroll
        for (int it = 0; it < (BN * BK / 4) / NT; it++) {
            int i = tid + it * NT;
            int n  = i / (BK / 4);
            int k4 = (i % (BK / 4)) * 4;
            float4 v = *reinterpret_cast<const float4*>(B + (size_t)(n0 + n) * K + kt + k4);
            Bs[k4 + 0][n] = v.x; Bs[k4 + 1][n] = v.y;
            Bs[k4 + 2][n] = v.z; Bs[k4 + 3][n] = v.w;
        }
        __syncthreads();

        #pragma unroll
        for (int k = 0; k < BK; k++) {
            float a[TM], b[TN];
            #pragma unroll
            for (int i = 0; i < TM; i++) a[i] = As[k][ty * TM + i];
            #pragma unroll
            for (int j = 0; j < TN; j++) b[j] = Bs[k][tx * TN + j];
            #pragma unroll
            for (int i = 0; i < TM; i++)
                #pragma unroll
                for (int j = 0; j < TN; j++)
                    acc[i][j] = fmaf(a[i], b[j], acc[i][j]);
        }
        __syncthreads();
    }

    #pragma unroll
    for (int i = 0; i < TM; i++) {
        int gm = m0 + ty * TM + i;
        if (gm >= M) continue;
        #pragma unroll
        for (int j = 0; j < TN; j++) {
            int gn = n0 + tx * TN + j;
            float v = acc[i][j];
            if (Cinit) v += Cinit[(size_t)gm * N + gn];
            if (bias0) v += bias0[gn];
            if (bias1) v += bias1[gn];
            C[(size_t)gm * N + gn] = v;
        }
    }
}

// ---------------- launch --------------------------------------------------
extern "C" void kernel_launch(void* const* d_in, const int* in_sizes, int n_in,
                              void* d_out, int out_size) {
    const float* features = (const float*)d_in[0];
    const int*   captions = (const int*)  d_in[1];
    const int*   lengths  = (const int*)  d_in[2];
    const float* h0       = (const float*)d_in[3];
    const float* c0       = (const float*)d_in[4];
    const float* embed_w  = (const float*)d_in[5];
    const float* w_ih     = (const float*)d_in[6];
    const float* w_hh     = (const float*)d_in[7];
    const float* b_ih     = (const float*)d_in[8];
    const float* b_hh     = (const float*)d_in[9];
    const float* lin_w    = (const float*)d_in[10];
    const float* lin_b    = (const float*)d_in[11];
    float* out = (float*)d_out;

    const int M_total = out_size / VOCAB;   // total packed rows (sum of lengths)

    float *xseq, *xw, *gates, *hstate, *cstate, *hall, *hc;
    int* off;
    cudaGetSymbolAddress((void**)&xseq,   d_xseq);
    cudaGetSymbolAddress((void**)&xw,     d_xw);
    cudaGetSymbolAddress((void**)&gates,  d_gates);
    cudaGetSymbolAddress((void**)&hstate, d_hstate);
    cudaGetSymbolAddress((void**)&cstate, d_cstate);
    cudaGetSymbolAddress((void**)&hall,   d_hall);
    cudaGetSymbolAddress((void**)&hc,     d_hc);
    cudaGetSymbolAddress((void**)&off,    d_off);

    // init recurrent state
    cudaMemcpyAsync(hstate, h0, BATCH * HDIM * sizeof(float), cudaMemcpyDeviceToDevice, 0);
    cudaMemcpyAsync(cstate, c0, BATCH * HDIM * sizeof(float), cudaMemcpyDeviceToDevice, 0);

    // pack offsets
    compute_off_kernel<<<1, 128>>>(lengths, off);

    // teacher-forced inputs
    build_xseq_kernel<<<(TSTEPS * BATCH * EDIM / 4) / 256, 256>>>(features, captions, embed_w, xseq);

    // xW = X @ w_ih^T + (b_ih + b_hh)   [2560, 2048]
    gemm_nt_kernel<128, 128, 16, 8, 8>
        <<<dim3(GDIM / 128, (TSTEPS * BATCH) / 128), 256>>>(
            xseq, w_ih, nullptr, b_ih, b_hh, xw, TSTEPS * BATCH, GDIM, EDIM);

    // sequential recurrence
    for (int t = 0; t < TSTEPS; t++) {
        gemm_nt_kernel<64, 64, 16, 4, 4>
            <<<dim3(GDIM / 64, BATCH / 64), 256>>>(
                hstate, w_hh, xw + (size_t)t * BATCH * GDIM, nullptr, nullptr,
                gates, BATCH, GDIM, HDIM);
        lstm_cell_kernel<<<(BATCH * HDIM) / 256, 256>>>(
            gates, hstate, cstate, hall + (size_t)t * BATCH * HDIM);
    }

    // gather packed rows
    gather_h_kernel<<<TSTEPS * BATCH, 128>>>(hall, off, hc);

    // out = Hc @ lin_w^T + lin_b   [M_total, 32000]
    gemm_nt_kernel<128, 128, 16, 8, 8>
        <<<dim3(VOCAB / 128, (M_total + 127) / 128), 256>>>(
            hc, lin_w, nullptr, lin_b, nullptr, out, M_total, VOCAB, HDIM);
}

// round 3
// speedup vs baseline: 2.7623x; 2.7623x over previous
#include <cuda_runtime.h>
#include <cstdint>
#include <math.h>

#define TSTEPS 20
#define BATCH  128
#define EDIM   512
#define HDIM   512
#define GDIM   2048   // 4*HDIM
#define VOCAB  32000
#define CAPLEN 20

// tcgen05 is only legal in the arch-specific (sm_103a) compilation pass.
#if defined(__CUDA_ARCH__) && (__CUDA_ARCH__ == 1030) && \
    (defined(__CUDA_ARCH_FEAT_SM103_ALL) || defined(__CUDA_ARCH_SPECIFIC__))
#define HAS_TCGEN05 1
#else
#define HAS_TCGEN05 0
#endif

// ==================== minimal PTX helpers (sm_103a only) ====================
__device__ __forceinline__ uint32_t smem_to_u32(const void* smem_ptr) {
    uint32_t addr;
    asm("{ .reg .u64 tmp; cvta.to.shared.u64 tmp, %1; cvt.u32.u64 %0, tmp; }"
        : "=r"(addr) : "l"(smem_ptr));
    return addr;
}

#if HAS_TCGEN05
__device__ __forceinline__ uint32_t elect_one_pred() {
    uint32_t pred;
    asm volatile(
        "{\n\t.reg .pred p;\n\telect.sync _|p, 0xFFFFFFFF;\n\t"
        "selp.b32 %0, 1, 0, p;\n\t}" : "=r"(pred));
    return pred;
}
#define TCGEN05_ALLOC(smem_result_addr, nCols) \
    asm volatile("tcgen05.alloc.cta_group::1.sync.aligned.shared::cta.b32 [%0], %1;" \
        :: "r"((uint32_t)(smem_result_addr)), "r"((uint32_t)(nCols)) : "memory")
#define TCGEN05_DEALLOC(tmem_addr, nCols) \
    asm volatile("tcgen05.dealloc.cta_group::1.sync.aligned.b32 %0, %1;" \
        :: "r"(tmem_addr), "r"((uint32_t)(nCols)))
#define TCGEN05_RELINQUISH_ALLOC_PERMIT() \
    asm volatile("tcgen05.relinquish_alloc_permit.cta_group::1.sync.aligned;")
#define TCGEN05_COMMIT(mbar_smem_addr) \
    asm volatile("tcgen05.commit.cta_group::1.mbarrier::arrive::one.shared::cluster.b64 [%0];" \
        :: "r"((uint32_t)(mbar_smem_addr)) : "memory")
#define TCGEN05_WAIT_LD() asm volatile("tcgen05.wait::ld.sync.aligned;" ::: "memory")
#define TCGEN05_FENCE_AFTER() asm volatile("tcgen05.fence::after_thread_sync;" ::: "memory")
#define FENCE_PROXY_ASYNC_SHARED_CTA() \
    asm volatile("fence.proxy.async.shared::cta;" ::: "memory")
#define MBARRIER_INIT(mbar_smem_addr, count) \
    asm volatile("mbarrier.init.shared.b64 [%0], %1;" \
        :: "r"((uint32_t)(mbar_smem_addr)), "r"((uint32_t)(count)) : "memory")
#define MBARRIER_INVAL(mbar_smem_addr) \
    asm volatile("mbarrier.inval.shared.b64 [%0];" :: "r"((uint32_t)(mbar_smem_addr)) : "memory")
#define MBARRIER_WAIT_PARITY(mbar_smem_addr, phase_parity) do { \
    uint32_t _mbar = (uint32_t)(mbar_smem_addr); \
    uint32_t _parity = (uint32_t)(phase_parity); \
    uint32_t _done; \
    asm volatile("{\n\t.reg .pred p;\n\t" \
        "mbarrier.try_wait.parity.acquire.cta.shared::cta.b64 p, [%1], %2;\n\t" \
        "selp.b32 %0, 1, 0, p;\n\t}" : "=r"(_done) : "r"(_mbar), "r"(_parity) : "memory"); \
    if (!_done) { \
        asm volatile("{\n\t.reg .pred P1;\n\t" \
            "WAIT_LOOP_%=:\n\t" \
            "mbarrier.try_wait.parity.acquire.cta.shared::cta.b64 P1, [%0], %1, 0x989680;\n\t" \
            "@P1 bra.uni WAIT_DONE_%=;\n\t" \
            "bra.uni WAIT_LOOP_%=;\n\t" \
            "WAIT_DONE_%=:\n\t}" :: "r"(_mbar), "r"(_parity) : "memory"); \
    } \
} while(0)
#define TCGEN05_LD_32X32B_X32(r, tmem_addr) \
    asm volatile("tcgen05.ld.sync.aligned.32x32b.x32.b32 " \
        "{%0, %1, %2, %3, %4, %5, %6, %7, " \
        " %8, %9, %10, %11, %12, %13, %14, %15, " \
        " %16, %17, %18, %19, %20, %21, %22, %23, " \
        " %24, %25, %26, %27, %28, %29, %30, %31}, [%32];" \
        : "=r"((r)[0]),  "=r"((r)[1]),  "=r"((r)[2]),  "=r"((r)[3]), \
          "=r"((r)[4]),  "=r"((r)[5]),  "=r"((r)[6]),  "=r"((r)[7]), \
          "=r"((r)[8]),  "=r"((r)[9]),  "=r"((r)[10]), "=r"((r)[11]), \
          "=r"((r)[12]), "=r"((r)[13]), "=r"((r)[14]), "=r"((r)[15]), \
          "=r"((r)[16]), "=r"((r)[17]), "=r"((r)[18]), "=r"((r)[19]), \
          "=r"((r)[20]), "=r"((r)[21]), "=r"((r)[22]), "=r"((r)[23]), \
          "=r"((r)[24]), "=r"((r)[25]), "=r"((r)[26]), "=r"((r)[27]), \
          "=r"((r)[28]), "=r"((r)[29]), "=r"((r)[30]), "=r"((r)[31]) \
        : "r"(tmem_addr))

#define TCGEN05_MMA_TF32_SS(d_tmem, a_desc, b_desc, idesc, enable_d) do { \
    uint32_t _en = (enable_d) ? 1u : 0u; \
    asm volatile("{\n\t.reg .pred p;\n\tsetp.ne.u32 p, %4, 0;\n\t" \
        "tcgen05.mma.cta_group::1.kind::tf32 [%0], %1, %2, %3, {%5, %5, %5, %5}, p;\n\t}" \
        :: "r"(d_tmem), "l"(a_desc), "l"(b_desc), "r"(idesc), "r"(_en), "r"(0u) \
        : "memory"); \
} while(0)

static __device__ __forceinline__ uint64_t make_sw128_desc(uint32_t base_addr) {
    // layout SW128 (2<<61), version 1 (1<<46), SBO=64, LBO=1
    uint64_t d = (uint64_t(2) << 61) | (uint64_t(1) << 46) |
                 (uint64_t(64) << 32) | (uint64_t(1) << 16);
    return d | ((uint64_t)(base_addr >> 4) & 0x3FFF);
}
#endif  // HAS_TCGEN05

// ==================== device scratch ====================
__device__ float d_xseq [TSTEPS * BATCH * EDIM];
__device__ float d_xw   [TSTEPS * BATCH * GDIM];
__device__ float d_gates[BATCH * GDIM];
__device__ float d_hstate[BATCH * HDIM];
__device__ float d_cstate[BATCH * HDIM];
__device__ float d_hall [TSTEPS * BATCH * HDIM];
__device__ float d_hc   [TSTEPS * BATCH * HDIM];
__device__ int   d_off  [TSTEPS + 1];

// ==================== small kernels ====================
__global__ void compute_off_kernel(const int* __restrict__ lengths,
                                   int* __restrict__ off) {
    __shared__ int sl[BATCH];
    __shared__ int cnt[TSTEPS];
    int tid = threadIdx.x;
    if (tid < BATCH) sl[tid] = lengths[tid];
    __syncthreads();
    if (tid < TSTEPS) {
        int c = 0;
        #pragma unroll 8
        for (int b = 0; b < BATCH; b++) c += (sl[b] > tid);
        cnt[tid] = c;
    }
    __syncthreads();
    if (tid == 0) {
        int acc = 0;
        for (int t = 0; t < TSTEPS; t++) { off[t] = acc; acc += cnt[t]; }
        off[TSTEPS] = acc;
    }
}

__global__ void build_xseq_kernel(const float* __restrict__ features,
                                  const int*   __restrict__ captions,
                                  const float* __restrict__ embed_w,
                                  float* __restrict__ xseq) {
    int gid = blockIdx.x * blockDim.x + threadIdx.x;
    int e4  = gid % (EDIM / 4);
    int row = gid / (EDIM / 4);
    int t = row / BATCH, b = row % BATCH;
    const float4* src;
    if (t == 0) {
        src = reinterpret_cast<const float4*>(features + (size_t)b * EDIM);
    } else {
        int tok = captions[b * CAPLEN + (t - 1)];
        src = reinterpret_cast<const float4*>(embed_w + (size_t)tok * EDIM);
    }
    reinterpret_cast<float4*>(xseq)[gid] = src[e4];
}

__global__ void lstm_cell_kernel(const float* __restrict__ gates,
                                 float* __restrict__ h,
                                 float* __restrict__ c,
                                 float* __restrict__ hout) {
    int idx = blockIdx.x * blockDim.x + threadIdx.x;
    int b = idx / HDIM, j = idx % HDIM;
    const float* g = gates + (size_t)b * GDIM + j;
    float ig = 1.0f / (1.0f + expf(-g[0]));
    float fg = 1.0f / (1.0f + expf(-g[HDIM]));
    float gg = tanhf(g[2 * HDIM]);
    float og = 1.0f / (1.0f + expf(-g[3 * HDIM]));
    float cc = fg * c[idx] + ig * gg;
    c[idx] = cc;
    float hh = og * tanhf(cc);
    h[idx] = hh;
    hout[idx] = hh;
}

__global__ void gather_h_kernel(const float* __restrict__ hall,
                                const int* __restrict__ off,
                                float* __restrict__ hc) {
    int row = blockIdx.x;
    int t = row / BATCH, b = row % BATCH;
    int cnt = off[t + 1] - off[t];
    if (b >= cnt) return;
    const float4* src = reinterpret_cast<const float4*>(hall + (size_t)row * HDIM);
    float4*       dst = reinterpret_cast<float4*>(hc + (size_t)(off[t] + b) * HDIM);
    dst[threadIdx.x] = src[threadIdx.x];
}

// ==================== fp32 SIMT GEMM (for xW) ====================
template<int BM, int BN, int BK, int TM, int TN>
__global__ void __launch_bounds__((BM / TM) * (BN / TN))
gemm_nt_kernel(const float* __restrict__ A, const float* __restrict__ B,
               const float* __restrict__ bias0, const float* __restrict__ bias1,
               float* __restrict__ C, int M, int N, int K) {
    constexpr int NT = (BM / TM) * (BN / TN);
    __shared__ float As[BK][BM];
    __shared__ float Bs[BK][BN];
    const int tid = threadIdx.x;
    const int m0 = blockIdx.y * BM;
    const int n0 = blockIdx.x * BN;
    const int tx = tid % (BN / TN);
    const int ty = tid / (BN / TN);
    float acc[TM][TN];
    #pragma unroll
    for (int i = 0; i < TM; i++)
        #pragma unroll
        for (int j = 0; j < TN; j++) acc[i][j] = 0.0f;

    for (int kt = 0; kt < K; kt += BK) {
        #pragma unroll
        for (int it = 0; it < (BM * BK / 4) / NT; it++) {
            int i = tid + it * NT;
            int m  = i / (BK / 4);
            int k4 = (i % (BK / 4)) * 4;
            float4 v = make_float4(0.f, 0.f, 0.f, 0.f);
            if (m0 + m < M)
                v = *reinterpret_cast<const float4*>(A + (size_t)(m0 + m) * K + kt + k4);
            As[k4 + 0][m] = v.x; As[k4 + 1][m] = v.y;
            As[k4 + 2][m] = v.z; As[k4 + 3][m] = v.w;
        }
        #pragma unroll
        for (int it = 0; it < (BN * BK / 4) / NT; it++) {
            int i = tid + it * NT;
            int n  = i / (BK / 4);
            int k4 = (i % (BK / 4)) * 4;
            float4 v = *reinterpret_cast<const float4*>(B + (size_t)(n0 + n) * K + kt + k4);
            Bs[k4 + 0][n] = v.x; Bs[k4 + 1][n] = v.y;
            Bs[k4 + 2][n] = v.z; Bs[k4 + 3][n] = v.w;
        }
        __syncthreads();
        #pragma unroll
        for (int k = 0; k < BK; k++) {
            float a[TM], b[TN];
            #pragma unroll
            for (int i = 0; i < TM; i++) a[i] = As[k][ty * TM + i];
            #pragma unroll
            for (int j = 0; j < TN; j++) b[j] = Bs[k][tx * TN + j];
            #pragma unroll
            for (int i = 0; i < TM; i++)
                #pragma unroll
                for (int j = 0; j < TN; j++)
                    acc[i][j] = fmaf(a[i], b[j], acc[i][j]);
        }
        __syncthreads();
    }
    #pragma unroll
    for (int i = 0; i < TM; i++) {
        int gm = m0 + ty * TM + i;
        if (gm >= M) continue;
        #pragma unroll
        for (int j = 0; j < TN; j++) {
            int gn = n0 + tx * TN + j;
            float v = acc[i][j];
            if (bias0) v += bias0[gn];
            if (bias1) v += bias1[gn];
            C[(size_t)gm * N + gn] = v;
        }
    }
}

// ==================== fp32 split-K GEMM (recurrence), atomic epilogue ====
template<int BM, int BN, int BK, int TM, int TN>
__global__ void __launch_bounds__((BM / TM) * (BN / TN))
gemm_nt_splitk_kernel(const float* __restrict__ A, const float* __restrict__ B,
                      float* __restrict__ C, int M, int N, int K, int klen) {
    constexpr int NT = (BM / TM) * (BN / TN);
    __shared__ float As[BK][BM];
    __shared__ float Bs[BK][BN];
    const int tid = threadIdx.x;
    const int m0 = blockIdx.y * BM;
    const int n0 = blockIdx.x * BN;
    const int k0 = blockIdx.z * klen;
    const int tx = tid % (BN / TN);
    const int ty = tid / (BN / TN);
    float acc[TM][TN];
    #pragma unroll
    for (int i = 0; i < TM; i++)
        #pragma unroll
        for (int j = 0; j < TN; j++) acc[i][j] = 0.0f;

    for (int kt = k0; kt < k0 + klen; kt += BK) {
        #pragma unroll
        for (int it = 0; it < (BM * BK / 4) / NT; it++) {
            int i = tid + it * NT;
            int m  = i / (BK / 4);
            int k4 = (i % (BK / 4)) * 4;
            float4 v = *reinterpret_cast<const float4*>(A + (size_t)(m0 + m) * K + kt + k4);
            As[k4 + 0][m] = v.x; As[k4 + 1][m] = v.y;
            As[k4 + 2][m] = v.z; As[k4 + 3][m] = v.w;
        }
        #pragma unroll
        for (int it = 0; it < (BN * BK / 4) / NT; it++) {
            int i = tid + it * NT;
            int n  = i / (BK / 4);
            int k4 = (i % (BK / 4)) * 4;
            float4 v = *reinterpret_cast<const float4*>(B + (size_t)(n0 + n) * K + kt + k4);
            Bs[k4 + 0][n] = v.x; Bs[k4 + 1][n] = v.y;
            Bs[k4 + 2][n] = v.z; Bs[k4 + 3][n] = v.w;
        }
        __syncthreads();
        #pragma unroll
        for (int k = 0; k < BK; k++) {
            float a[TM], b[TN];
            #pragma unroll
            for (int i = 0; i < TM; i++) a[i] = As[k][ty * TM + i];
            #pragma unroll
            for (int j = 0; j < TN; j++) b[j] = Bs[k][tx * TN + j];
            #pragma unroll
            for (int i = 0; i < TM; i++)
                #pragma unroll
                for (int j = 0; j < TN; j++)
                    acc[i][j] = fmaf(a[i], b[j], acc[i][j]);
        }
        __syncthreads();
    }
    #pragma unroll
    for (int i = 0; i < TM; i++) {
        int gm = m0 + ty * TM + i;
        #pragma unroll
        for (int j = 0; j < TN; j++) {
            int gn = n0 + tx * TN + j;
            atomicAdd(&C[(size_t)gm * N + gn], acc[i][j]);
        }
    }
}

// ==================== projection GEMM: tcgen05 tf32 (sm_103a) ====================
// C[M,N] = A[M,K] @ B[N,K]^T + bias,  tiles 128x128, K chunks of 64.
// idesc: dtype F32(1), atype/btype TF32(2), N=128 (N>>3 @17), M=128 (M>>4 @24)
#define IDESC_TF32 ((1u << 4) | (2u << 7) | (2u << 10) | (16u << 17) | (8u << 24))

__device__ __forceinline__ uint32_t tile_swz_off(int r, int kk) {
    // blocked SW128 atoms: atom = 8 rows x 32 tf32 (128B rows); 16 atom-rows, 2 atom-cols
    uint32_t byte = (uint32_t)(((r >> 3) + ((kk >> 5) << 4)) << 10)
                  + (uint32_t)((r & 7) << 7) + (uint32_t)((kk & 31) << 2);
    return byte ^ ((byte >> 3) & 0x70);
}

__global__ void __launch_bounds__(256, 1)
proj_tf32_kernel(const float* __restrict__ A, const float* __restrict__ B,
                 const float* __restrict__ bias, float* __restrict__ C,
                 int M, int N, int K) {
    extern __shared__ float dsm[];
    const int tid = threadIdx.x, wid = tid >> 5, lid = tid & 31;
    const int m0 = blockIdx.x * 128;
    const int n0 = blockIdx.y * 128;

#if HAS_TCGEN05
    __shared__ uint32_t s_tmem[2];
    __shared__ __align__(8) uint64_t s_mbar;
    __shared__ float s_bias[128];

    uint32_t dyn_u32 = smem_to_u32(dsm);
    uint32_t base_u32 = (dyn_u32 + 1023u) & ~1023u;
    char* basep = (char*)dsm + (base_u32 - dyn_u32);
    char* aA = basep;
    char* aB = basep + 32768;
    float* Ds = (float*)basep;                 // epilogue reuse, pitch 132 floats
    uint32_t aA_u = base_u32, aB_u = base_u32 + 32768;
    uint32_t mbar = smem_to_u32(&s_mbar);

    if (tid < 128) s_bias[tid] = bias[n0 + tid];
    if (tid == 0) MBARRIER_INIT(mbar, 1);
    if (wid == 0) {
        TCGEN05_ALLOC(smem_to_u32(&s_tmem[0]), 128);
        TCGEN05_RELINQUISH_ALLOC_PERMIT();
    }
    __syncthreads();
    const uint32_t tmem = s_tmem[0];

    const int nchunks = K / 64;
    for (int ch = 0; ch < nchunks; ch++) {
        const int kt = ch * 64;
        // load A,B tiles (128 rows x 64 cols each); 256 thr * 8 it * float4
        #pragma unroll
        for (int it = 0; it < 8; it++) {
            int i = tid + (it << 8);
            int r  = i >> 4;
            int kk = (i & 15) << 2;
            uint32_t off = tile_swz_off(r, kk);
            float4 va = *reinterpret_cast<const float4*>(A + (size_t)(m0 + r) * K + kt + kk);
            *reinterpret_cast<float4*>(aA + off) = va;
            float4 vb = *reinterpret_cast<const float4*>(B + (size_t)(n0 + r) * K + kt + kk);
            *reinterpret_cast<float4*>(aB + off) = vb;
        }
        __syncthreads();
        if (wid == 0) {
            if (elect_one_pred()) {
                FENCE_PROXY_ASYNC_SHARED_CTA();
                uint64_t ad = make_sw128_desc(aA_u);
                uint64_t bd = make_sw128_desc(aB_u);
                const uint32_t ksoff[8] = {0, 2, 4, 6, 1024, 1026, 1028, 1030};
                #pragma unroll
                for (int s = 0; s < 8; s++) {
                    TCGEN05_MMA_TF32_SS(tmem, ad + ksoff[s], bd + ksoff[s],
                                        IDESC_TF32, (ch > 0) || (s > 0));
                }
                TCGEN05_COMMIT(mbar);
            }
        }
        MBARRIER_WAIT_PARITY(mbar, ch & 1);
        __syncthreads();
        // after wait, MMA finished reading SMEM -> safe to overwrite next chunk
    }
    TCGEN05_FENCE_AFTER();

    // epilogue: TMEM -> SMEM (pitch 132 floats) -> coalesced GMEM
    if (wid < 4) {
        const int row = (wid << 5) + lid;
        #pragma unroll
        for (int cb = 0; cb < 128; cb += 32) {
            uint32_t r[32];
            TCGEN05_LD_32X32B_X32(r, tmem + cb);
            TCGEN05_WAIT_LD();
            #pragma unroll
            for (int q = 0; q < 8; q++) {
                float4 v;
                v.x = __uint_as_float(r[4 * q + 0]);
                v.y = __uint_as_float(r[4 * q + 1]);
                v.z = __uint_as_float(r[4 * q + 2]);
                v.w = __uint_as_float(r[4 * q + 3]);
                *reinterpret_cast<float4*>(&Ds[row * 132 + cb + 4 * q]) = v;
            }
        }
    }
    __syncthreads();
    #pragma unroll
    for (int it = 0; it < 16; it++) {
        int i = tid + (it << 8);
        int r  = i >> 5;
        int c4 = (i & 31) << 2;
        int gm = m0 + r;
        if (gm < M) {
            float4 v = *reinterpret_cast<const float4*>(&Ds[r * 132 + c4]);
            float4 b = *reinterpret_cast<const float4*>(&s_bias[c4]);
            v.x += b.x; v.y += b.y; v.z += b.z; v.w += b.w;
            *reinterpret_cast<float4*>(&C[(size_t)gm * N + n0 + c4]) = v;
        }
    }
    __syncthreads();
    if (tid == 0) MBARRIER_INVAL(mbar);
    if (wid == 0) TCGEN05_DEALLOC(tmem, 128);

#else  // ------- SIMT fp32 fallback (compiled for plain sm_103 pass) -------
    float* As = dsm;                 // [16][128]
    float* Bs = dsm + 16 * 128;      // [16][128]
    const int tx = tid % 16;
    const int ty = tid / 16;
    float acc[8][8];
    #pragma unroll
    for (int i = 0; i < 8; i++)
        #pragma unroll
        for (int j = 0; j < 8; j++) acc[i][j] = 0.0f;

    for (int kt = 0; kt < K; kt += 16) {
        #pragma unroll
        for (int it = 0; it < 2; it++) {
            int i = tid + it * 256;
            int m  = i / 4;
            int k4 = (i % 4) * 4;
            float4 va = *reinterpret_cast<const float4*>(A + (size_t)(m0 + m) * K + kt + k4);
            As[(k4 + 0) * 128 + m] = va.x; As[(k4 + 1) * 128 + m] = va.y;
            As[(k4 + 2) * 128 + m] = va.z; As[(k4 + 3) * 128 + m] = va.w;
            float4 vb = *reinterpret_cast<const float4*>(B + (size_t)(n0 + m) * K + kt + k4);
            Bs[(k4 + 0) * 128 + m] = vb.x; Bs[(k4 + 1) * 128 + m] = vb.y;
            Bs[(k4 + 2) * 128 + m] = vb.z; Bs[(k4 + 3) * 128 + m] = vb.w;
        }
        __syncthreads();
        #pragma unroll
        for (int k = 0; k < 16; k++) {
            float a[8], b[8];
            #pragma unroll
            for (int i = 0; i < 8; i++) a[i] = As[k * 128 + ty * 8 + i];
            #pragma unroll
            for (int j = 0; j < 8; j++) b[j] = Bs[k * 128 + tx * 8 + j];
            #pragma unroll
            for (int i = 0; i < 8; i++)
                #pragma unroll
                for (int j = 0; j < 8; j++)
                    acc[i][j] = fmaf(a[i], b[j], acc[i][j]);
        }
        __syncthreads();
    }
    #pragma unroll
    for (int i = 0; i < 8; i++) {
        int gm = m0 + ty * 8 + i;
        if (gm >= M) continue;
        #pragma unroll
        for (int j = 0; j < 8; j++) {
            int gn = n0 + tx * 8 + j;
            C[(size_t)gm * N + gn] = acc[i][j] + bias[gn];
        }
    }
#endif
}

// ==================== launch ====================
extern "C" void kernel_launch(void* const* d_in, const int* in_sizes, int n_in,
                              void* d_out, int out_size) {
    const float* features = (const float*)d_in[0];
    const int*   captions = (const int*)  d_in[1];
    const int*   lengths  = (const int*)  d_in[2];
    const float* h0       = (const float*)d_in[3];
    const float* c0       = (const float*)d_in[4];
    const float* embed_w  = (const float*)d_in[5];
    const float* w_ih     = (const float*)d_in[6];
    const float* w_hh     = (const float*)d_in[7];
    const float* b_ih     = (const float*)d_in[8];
    const float* b_hh     = (const float*)d_in[9];
    const float* lin_w    = (const float*)d_in[10];
    const float* lin_b    = (const float*)d_in[11];
    float* out = (float*)d_out;

    const int M_total = out_size / VOCAB;

    float *xseq, *xw, *gates, *hstate, *cstate, *hall, *hc;
    int* off;
    cudaGetSymbolAddress((void**)&xseq,   d_xseq);
    cudaGetSymbolAddress((void**)&xw,     d_xw);
    cudaGetSymbolAddress((void**)&gates,  d_gates);
    cudaGetSymbolAddress((void**)&hstate, d_hstate);
    cudaGetSymbolAddress((void**)&cstate, d_cstate);
    cudaGetSymbolAddress((void**)&hall,   d_hall);
    cudaGetSymbolAddress((void**)&hc,     d_hc);
    cudaGetSymbolAddress((void**)&off,    d_off);

    cudaMemcpyAsync(hstate, h0, BATCH * HDIM * sizeof(float), cudaMemcpyDeviceToDevice, 0);
    cudaMemcpyAsync(cstate, c0, BATCH * HDIM * sizeof(float), cudaMemcpyDeviceToDevice, 0);

    compute_off_kernel<<<1, 128>>>(lengths, off);
    build_xseq_kernel<<<(TSTEPS * BATCH * EDIM / 4) / 256, 256>>>(features, captions, embed_w, xseq);

    // xW = X @ w_ih^T + (b_ih + b_hh)   [2560, 2048] fp32
    gemm_nt_kernel<128, 128, 16, 8, 8>
        <<<dim3(GDIM / 128, (TSTEPS * BATCH) / 128), 256>>>(
            xseq, w_ih, b_ih, b_hh, xw, TSTEPS * BATCH, GDIM, EDIM);

    // sequential recurrence: gates = xw[t] + h @ w_hh^T  (split-K fp32 + atomics)
    for (int t = 0; t < TSTEPS; t++) {
        cudaMemcpyAsync(gates, xw + (size_t)t * BATCH * GDIM,
                        (size_t)BATCH * GDIM * sizeof(float),
                        cudaMemcpyDeviceToDevice, 0);
        gemm_nt_splitk_kernel<64, 64, 16, 4, 4>
            <<<dim3(GDIM / 64, BATCH / 64, 8), 256>>>(
                hstate, w_hh, gates, BATCH, GDIM, HDIM, HDIM / 8);
        lstm_cell_kernel<<<(BATCH * HDIM) / 256, 256>>>(
            gates, hstate, cstate, hall + (size_t)t * BATCH * HDIM);
    }

    gather_h_kernel<<<TSTEPS * BATCH, 128>>>(hall, off, hc);

    // projection: out = Hc @ lin_w^T + lin_b   [M_total, 32000]
    const int smem_bytes = 68608;  // align pad + max(A+B=64KB, Ds=128*132*4)
    cudaFuncSetAttribute(proj_tf32_kernel,
                         cudaFuncAttributeMaxDynamicSharedMemorySize, smem_bytes);
    proj_tf32_kernel<<<dim3((M_total + 127) / 128, VOCAB / 128), 256, smem_bytes>>>(
        hc, lin_w, lin_b, out, M_total, VOCAB, HDIM);
}